// round 1
// baseline (speedup 1.0000x reference)
#include <cuda_runtime.h>

#define BATCH 4
#define CIN   64
#define HH    128
#define WW    128
#define N9    9
#define OFFC  18
#define COUT  64
#define KDIM  576   // CIN * 9

// Scratch (static device globals — no runtime allocation)
__device__ float g_x_nhwc[BATCH * HH * WW * CIN];   // 16.8 MB
__device__ float g_off[BATCH * HH * WW * OFFC];     // 4.7 MB

// ---------------------------------------------------------------------------
// K0: NCHW -> NHWC transpose of x
// ---------------------------------------------------------------------------
__global__ void k_transpose(const float* __restrict__ x) {
    __shared__ float t[32][33];
    int b = blockIdx.z >> 7;
    int h = blockIdx.z & 127;
    int w0 = blockIdx.x * 32;
    int c0 = blockIdx.y * 32;
    int tx = threadIdx.x, ty = threadIdx.y;
#pragma unroll
    for (int r = 0; r < 32; r += 8)
        t[ty + r][tx] = x[(((b * CIN) + (c0 + ty + r)) * HH + h) * WW + w0 + tx];
    __syncthreads();
#pragma unroll
    for (int r = 0; r < 32; r += 8)
        g_x_nhwc[(((b * HH) + h) * WW + (w0 + ty + r)) * CIN + c0 + tx] = t[tx][ty + r];
}

// ---------------------------------------------------------------------------
// K1: offset conv (18ch 3x3 conv + bias), output reordered [rows(9), cols(9)]
// smem: x tile CHW [64][18][18] + W_off transposed [576][18]
// ---------------------------------------------------------------------------
#define K1_SMEM_BYTES ((64 * 324 + 18 * 576) * 4)

__global__ void k_offsets(const float* __restrict__ x,
                          const float* __restrict__ Woff,
                          const float* __restrict__ boff) {
    extern __shared__ float sm1[];
    float* xs = sm1;              // [c][li][lj] : 64*18*18
    float* ws = sm1 + 64 * 324;   // [k][o]      : 576*18

    int b  = blockIdx.z;
    int i0 = blockIdx.y * 16;
    int j0 = blockIdx.x * 16;
    int tid = threadIdx.x;

    for (int e = tid; e < 64 * 324; e += 256) {
        int c = e / 324;
        int rem = e - c * 324;
        int li = rem / 18, lj = rem - li * 18;
        int gi = i0 + li - 1, gj = j0 + lj - 1;
        float v = 0.f;
        if ((unsigned)gi < 128u && (unsigned)gj < 128u)
            v = x[((b * 64 + c) * 128 + gi) * 128 + gj];
        xs[e] = v;
    }
    for (int e = tid; e < 18 * 576; e += 256) {
        int o = e / 576;
        int k = e - o * 576;
        ws[k * 18 + o] = Woff[e];
    }
    __syncthreads();

    int ty = tid >> 4, tx = tid & 15;
    float acc[18];
#pragma unroll
    for (int o = 0; o < 18; o++) acc[o] = __ldg(&boff[o]);

    for (int c = 0; c < 64; c++) {
        float xv[9];
#pragma unroll
        for (int t = 0; t < 9; t++)
            xv[t] = xs[c * 324 + (ty + t / 3) * 18 + (tx + t % 3)];
#pragma unroll
        for (int t = 0; t < 9; t++) {
            const float* wp = ws + (c * 9 + t) * 18;
#pragma unroll
            for (int o = 0; o < 18; o++)
                acc[o] += wp[o] * xv[t];
        }
    }
    // reorder: new[n] = old[2n] (row offsets), new[9+n] = old[2n+1] (col offsets)
    float* op = g_off + (((b * 128) + i0 + ty) * 128 + (j0 + tx)) * 18;
#pragma unroll
    for (int n = 0; n < 9; n++) {
        op[n]     = acc[2 * n];
        op[9 + n] = acc[2 * n + 1];
    }
}

// ---------------------------------------------------------------------------
// K2: persistent. W_conv staged once in smem as [k][co] (padded rows of 68).
// Per 16-pixel tile: taps -> sample S[16][576] -> GEMM -> coalesced store.
// ---------------------------------------------------------------------------
#define SM2_WS (576 * 68)     // floats
#define SM2_S  (16 * 580)
#define SM2_OS (64 * 17)
#define K2_SMEM_BYTES ((SM2_WS + SM2_S + SM2_OS + 144 * 4) * 4 + 144 * 4 * 4)

__global__ void __launch_bounds__(256, 1) k_main(const float* __restrict__ Wc,
                                                 float* __restrict__ out) {
    extern __shared__ float sm2[];
    float* Ws   = sm2;                 // [576][68]  W_conv transposed, padded
    float* S    = Ws + SM2_WS;         // [16][580]  sampled values
    float* Os   = S + SM2_S;           // [64][17]   output staging
    float* tw   = Os + SM2_OS;         // [144][4]   tap weights
    int*   tixs = (int*)(tw + 144 * 4);// [144][4]   tap indices (floats into NHWC plane)

    int tid = threadIdx.x;

    // Stage W once: Ws[k][co] = W_conv[co][k]
    for (int e = tid; e < COUT * KDIM; e += 256) {
        int co = e / 576;
        int k  = e - co * 576;
        Ws[k * 68 + co] = Wc[e];
    }

    for (int tile = blockIdx.x; tile < 4096; tile += gridDim.x) {
        int b   = tile >> 10;
        int rem = tile & 1023;
        int i   = rem >> 3;
        int j0  = (rem & 7) << 4;

        __syncthreads();  // Ws ready (1st iter); S/taps free from prior GEMM

        // --- taps: one thread per (px, n) ---
        if (tid < 144) {
            int px = tid / 9;
            int n  = tid - px * 9;
            const float* ofp = g_off + (((b * 128) + i) * 128 + (j0 + px)) * 18;
            float pr = (float)(i + n / 3) + ofp[n];          // (i+1) + (n/3 - 1)
            float pc = (float)(j0 + px + n % 3) + ofp[9 + n];

            float flr = floorf(pr);
            int   rl  = min(max((int)flr, 0), 129);
            int   rr  = min(max((int)flr + 1, 0), 129);
            float pm  = ((pr < 1.f) || (pr > 128.f)) ? flr : pr;
            pm = fminf(fmaxf(pm, 0.f), 129.f);
            float wrl = 1.f + ((float)rl - pm);
            float wrr = 1.f - ((float)rr - pm);

            float flc = floorf(pc);
            int   cl  = min(max((int)flc, 0), 129);
            int   cr  = min(max((int)flc + 1, 0), 129);
            float qm  = ((pc < 1.f) || (pc > 128.f)) ? flc : pc;
            qm = fminf(fmaxf(qm, 0.f), 129.f);
            float wcl = 1.f + ((float)cl - qm);
            float wcr = 1.f - ((float)cr - qm);

            int   rs[2]  = {rl, rr};
            float wr2[2] = {wrl, wrr};
            int   cs[2]  = {cl, cr};
            float wc2[2] = {wcl, wcr};
#pragma unroll
            for (int t = 0; t < 4; t++) {
                int R  = rs[t >> 1];
                int Cq = cs[t & 1];
                float w = wr2[t >> 1] * wc2[t & 1];
                bool ok = (R >= 1) && (R <= 128) && (Cq >= 1) && (Cq <= 128);
                tixs[tid * 4 + t] = ok ? ((R - 1) * 128 + (Cq - 1)) * 64 : 0;
                tw[tid * 4 + t]   = ok ? w : 0.f;  // padded region == 0
            }
        }
        __syncthreads();

        // --- sampling: 2304 tasks = 144 (px,n) x 16 channel-groups (float4) ---
        const float* xb = g_x_nhwc + b * (128 * 128 * 64);
#pragma unroll
        for (int it = 0; it < 9; it++) {
            int tt  = it * 256 + tid;
            int pn  = tt >> 4;
            int cig = tt & 15;
            int px  = pn / 9;
            int n   = pn - px * 9;
            float ax = 0.f, ay = 0.f, az = 0.f, aw = 0.f;
#pragma unroll
            for (int t = 0; t < 4; t++) {
                float w = tw[pn * 4 + t];
                const float4 v = *(const float4*)(xb + tixs[pn * 4 + t] + cig * 4);
                ax += w * v.x; ay += w * v.y; az += w * v.z; aw += w * v.w;
            }
            float* sp = S + px * 580 + (cig * 4) * 9 + n;
            sp[0] = ax; sp[9] = ay; sp[18] = az; sp[27] = aw;
        }
        __syncthreads();

        // --- GEMM: thread (px, cog) computes 1 px x 4 co ---
        {
            int px  = tid >> 4;
            int cog = tid & 15;
            const float* Srow = S + px * 580;
            float a0 = 0.f, a1 = 0.f, a2 = 0.f, a3 = 0.f;
#pragma unroll 8
            for (int k = 0; k < 576; k++) {
                float s = Srow[k];
                const float4 w = *(const float4*)(Ws + k * 68 + cog * 4);
                a0 += s * w.x; a1 += s * w.y; a2 += s * w.z; a3 += s * w.w;
            }
            Os[(cog * 4 + 0) * 17 + px] = a0;
            Os[(cog * 4 + 1) * 17 + px] = a1;
            Os[(cog * 4 + 2) * 17 + px] = a2;
            Os[(cog * 4 + 3) * 17 + px] = a3;
        }
        __syncthreads();

        // --- coalesced-ish NCHW store ---
        for (int e = tid; e < 1024; e += 256) {
            int co = e >> 4;
            int p2 = e & 15;
            out[((b * 64 + co) * 128 + i) * 128 + j0 + p2] = Os[co * 17 + p2];
        }
    }
}

// ---------------------------------------------------------------------------
extern "C" void kernel_launch(void* const* d_in, const int* in_sizes, int n_in,
                              void* d_out, int out_size) {
    const float* x    = (const float*)d_in[0];
    const float* Woff = (const float*)d_in[1];
    const float* boff = (const float*)d_in[2];
    const float* Wc   = (const float*)d_in[3];
    float* out = (float*)d_out;

    // Opt-in to large dynamic smem (idempotent, host-side, capture-safe)
    cudaFuncSetAttribute(k_offsets, cudaFuncAttributeMaxDynamicSharedMemorySize, K1_SMEM_BYTES);
    cudaFuncSetAttribute(k_main,    cudaFuncAttributeMaxDynamicSharedMemorySize, K2_SMEM_BYTES);

    dim3 tb0(32, 8);
    dim3 tg0(WW / 32, CIN / 32, BATCH * HH);
    k_transpose<<<tg0, tb0>>>(x);

    dim3 tg1(WW / 16, HH / 16, BATCH);
    k_offsets<<<tg1, 256, K1_SMEM_BYTES>>>(x, Woff, boff);

    k_main<<<148, 256, K2_SMEM_BYTES>>>(Wc, out);
}

// round 2
// speedup vs baseline: 1.3711x; 1.3711x over previous
#include <cuda_runtime.h>

#define BATCH 4
#define CIN   64
#define HH    128
#define WW    128
#define N9    9
#define OFFC  18
#define COUT  64
#define KDIM  576   // CIN * 9

// Scratch (static device globals — no runtime allocation)
__device__ float g_x_nhwc[BATCH * HH * WW * CIN];   // 16.8 MB
__device__ float g_off[BATCH * HH * WW * OFFC];     // 4.7 MB

// ---------------------------------------------------------------------------
// K0: NCHW -> NHWC transpose of x
// ---------------------------------------------------------------------------
__global__ void k_transpose(const float* __restrict__ x) {
    __shared__ float t[32][33];
    int b = blockIdx.z >> 7;
    int h = blockIdx.z & 127;
    int w0 = blockIdx.x * 32;
    int c0 = blockIdx.y * 32;
    int tx = threadIdx.x, ty = threadIdx.y;
#pragma unroll
    for (int r = 0; r < 32; r += 8)
        t[ty + r][tx] = x[(((b * CIN) + (c0 + ty + r)) * HH + h) * WW + w0 + tx];
    __syncthreads();
#pragma unroll
    for (int r = 0; r < 32; r += 8)
        g_x_nhwc[(((b * HH) + h) * WW + (w0 + ty + r)) * CIN + c0 + tx] = t[tx][ty + r];
}

// ---------------------------------------------------------------------------
// K1: offset conv (18ch 3x3 conv + bias), output reordered [rows(9), cols(9)]
// smem: x tile CHW [64][18][18] + W_off transposed [576][24] (padded, 16B rows)
// ---------------------------------------------------------------------------
#define K1_WS_STRIDE 24
#define K1_SMEM_BYTES ((64 * 324 + 576 * K1_WS_STRIDE) * 4)

__global__ void k_offsets(const float* __restrict__ x,
                          const float* __restrict__ Woff,
                          const float* __restrict__ boff) {
    extern __shared__ float sm1[];
    float* xs = sm1;              // [c][li][lj] : 64*18*18
    float* ws = sm1 + 64 * 324;   // [k][o pad24]

    int b  = blockIdx.z;
    int i0 = blockIdx.y * 16;
    int j0 = blockIdx.x * 16;
    int tid = threadIdx.x;

    for (int e = tid; e < 64 * 324; e += 256) {
        int c = e / 324;
        int rem = e - c * 324;
        int li = rem / 18, lj = rem - li * 18;
        int gi = i0 + li - 1, gj = j0 + lj - 1;
        float v = 0.f;
        if ((unsigned)gi < 128u && (unsigned)gj < 128u)
            v = x[((b * 64 + c) * 128 + gi) * 128 + gj];
        xs[e] = v;
    }
    for (int e = tid; e < 18 * 576; e += 256) {
        int o = e / 576;
        int k = e - o * 576;
        ws[k * K1_WS_STRIDE + o] = Woff[e];
    }
    __syncthreads();

    int ty = tid >> 4, tx = tid & 15;
    float acc[18];
#pragma unroll
    for (int o = 0; o < 18; o++) acc[o] = __ldg(&boff[o]);

    for (int c = 0; c < 64; c++) {
        float xv[9];
#pragma unroll
        for (int t = 0; t < 9; t++)
            xv[t] = xs[c * 324 + (ty + t / 3) * 18 + (tx + t % 3)];
#pragma unroll
        for (int t = 0; t < 9; t++) {
            const float* wp = ws + (c * 9 + t) * K1_WS_STRIDE;
#pragma unroll
            for (int q = 0; q < 4; q++) {
                float4 w4 = *(const float4*)(wp + q * 4);
                acc[q * 4 + 0] += w4.x * xv[t];
                acc[q * 4 + 1] += w4.y * xv[t];
                acc[q * 4 + 2] += w4.z * xv[t];
                acc[q * 4 + 3] += w4.w * xv[t];
            }
            float2 w2 = *(const float2*)(wp + 16);
            acc[16] += w2.x * xv[t];
            acc[17] += w2.y * xv[t];
        }
    }
    // reorder: new[n] = old[2n] (row offsets), new[9+n] = old[2n+1] (col offsets)
    float* op = g_off + (((b * 128) + i0 + ty) * 128 + (j0 + tx)) * 18;
#pragma unroll
    for (int n = 0; n < 9; n++) {
        op[n]     = acc[2 * n];
        op[9 + n] = acc[2 * n + 1];
    }
}

// ---------------------------------------------------------------------------
// K2: persistent. 32-pixel tiles. W_conv staged once in smem as [k][co].
// Per tile: taps -> sample S[32][577] -> f32x2 GEMM -> coalesced store.
// ---------------------------------------------------------------------------
#define SM2_WS   (576 * 64)      // 36864 fl = 144.0 KiB
#define SM2_S    (32 * 577)      // 18464 fl =  72.1 KiB
#define SM2_TAPS (288 * 8)       //  2304 fl =   9.0 KiB  (tw[1152] + tixs[1152]; Os aliases)
#define K2_SMEM_BYTES ((SM2_WS + SM2_S + SM2_TAPS) * 4)

__global__ void __launch_bounds__(256, 1) k_main(const float* __restrict__ Wc,
                                                 float* __restrict__ out) {
    extern __shared__ float sm2[];
    float* Ws   = sm2;                  // [576][64]  W_conv transposed
    float* S    = Ws + SM2_WS;          // [32][577]  sampled values
    float* tw   = S + SM2_S;            // [288][4]   tap weights
    int*   tixs = (int*)(tw + 288 * 4); // [288][4]   tap base indices (NHWC plane)
    float* Os   = tw;                   // [64][33]   output staging (aliases taps region)

    int tid = threadIdx.x;

    // Stage W once: Ws[k][co] = W_conv[co][k]
    for (int e = tid; e < COUT * KDIM; e += 256) {
        int co = e / 576;
        int k  = e - co * 576;
        Ws[k * 64 + co] = Wc[e];
    }

    for (int tile = blockIdx.x; tile < 2048; tile += gridDim.x) {
        int b   = tile >> 9;
        int rem = tile & 511;
        int i   = rem >> 2;
        int j0  = (rem & 3) << 5;

        __syncthreads();  // Ws ready (1st iter); S / Os free from prior tile

        // --- taps: one thread per (px, n), 288 pairs ---
        for (int pn = tid; pn < 288; pn += 256) {
            int px = pn / 9;
            int n  = pn - px * 9;
            const float* ofp = g_off + (((b * 128) + i) * 128 + (j0 + px)) * 18;
            float pr = (float)(i + n / 3) + ofp[n];          // (i+1) + (n/3 - 1)
            float pc = (float)(j0 + px + n % 3) + ofp[9 + n];

            float flr = floorf(pr);
            int   rl  = min(max((int)flr, 0), 129);
            int   rr  = min(max((int)flr + 1, 0), 129);
            float pm  = ((pr < 1.f) || (pr > 128.f)) ? flr : pr;
            pm = fminf(fmaxf(pm, 0.f), 129.f);
            float wrl = 1.f + ((float)rl - pm);
            float wrr = 1.f - ((float)rr - pm);

            float flc = floorf(pc);
            int   cl  = min(max((int)flc, 0), 129);
            int   cr  = min(max((int)flc + 1, 0), 129);
            float qm  = ((pc < 1.f) || (pc > 128.f)) ? flc : pc;
            qm = fminf(fmaxf(qm, 0.f), 129.f);
            float wcl = 1.f + ((float)cl - qm);
            float wcr = 1.f - ((float)cr - qm);

            int   rs[2]  = {rl, rr};
            float wr2[2] = {wrl, wrr};
            int   cs[2]  = {cl, cr};
            float wc2[2] = {wcl, wcr};
#pragma unroll
            for (int t = 0; t < 4; t++) {
                int R  = rs[t >> 1];
                int Cq = cs[t & 1];
                float w = wr2[t >> 1] * wc2[t & 1];
                bool ok = (R >= 1) && (R <= 128) && (Cq >= 1) && (Cq <= 128);
                tixs[pn * 4 + t] = ok ? ((R - 1) * 128 + (Cq - 1)) * 64 : 0;
                tw[pn * 4 + t]   = ok ? w : 0.f;  // out-of-pad taps contribute 0
            }
        }
        __syncthreads();

        // --- sampling: 4608 tasks = 288 (px,n) x 16 channel-groups (float4) ---
        const float* xb = g_x_nhwc + b * (128 * 128 * 64);
#pragma unroll
        for (int it = 0; it < 18; it++) {
            int tt  = it * 256 + tid;
            int pn  = tt >> 4;
            int cig = tt & 15;
            int px  = pn / 9;
            int n   = pn - px * 9;
            float ax = 0.f, ay = 0.f, az = 0.f, aw = 0.f;
#pragma unroll
            for (int t = 0; t < 4; t++) {
                float w = tw[pn * 4 + t];
                const float4 v = *(const float4*)(xb + tixs[pn * 4 + t] + cig * 4);
                ax += w * v.x; ay += w * v.y; az += w * v.z; aw += w * v.w;
            }
            float* sp = S + px * 577 + (cig * 4) * 9 + n;
            sp[0] = ax; sp[9] = ay; sp[18] = az; sp[27] = aw;
        }
        __syncthreads();

        // --- GEMM: thread (px = tid&31, cg = tid>>5) -> 8 co via f32x2 FFMA ---
        {
            int px = tid & 31;
            int cg = tid >> 5;                 // 0..7, co base cg*8
            const float* Srow = S + px * 577;
            const float* Wbase = Ws + cg * 8;
            unsigned long long a01 = 0ull, a23 = 0ull, a45 = 0ull, a67 = 0ull;
#pragma unroll 8
            for (int k = 0; k < 576; k++) {
                float s = Srow[k];
                unsigned long long ss;
                asm("mov.b64 %0, {%1, %1};" : "=l"(ss) : "f"(s));
                const float* wp = Wbase + k * 64;
                ulonglong2 w0 = *(const ulonglong2*)(wp);       // co (0,1),(2,3)
                ulonglong2 w1 = *(const ulonglong2*)(wp + 4);   // co (4,5),(6,7)
                asm("fma.rn.f32x2 %0, %1, %2, %0;" : "+l"(a01) : "l"(ss), "l"(w0.x));
                asm("fma.rn.f32x2 %0, %1, %2, %0;" : "+l"(a23) : "l"(ss), "l"(w0.y));
                asm("fma.rn.f32x2 %0, %1, %2, %0;" : "+l"(a45) : "l"(ss), "l"(w1.x));
                asm("fma.rn.f32x2 %0, %1, %2, %0;" : "+l"(a67) : "l"(ss), "l"(w1.y));
            }
            float o[8];
            asm("mov.b64 {%0, %1}, %2;" : "=f"(o[0]), "=f"(o[1]) : "l"(a01));
            asm("mov.b64 {%0, %1}, %2;" : "=f"(o[2]), "=f"(o[3]) : "l"(a23));
            asm("mov.b64 {%0, %1}, %2;" : "=f"(o[4]), "=f"(o[5]) : "l"(a45));
            asm("mov.b64 {%0, %1}, %2;" : "=f"(o[6]), "=f"(o[7]) : "l"(a67));
            __syncthreads();   // taps no longer needed; Os may overwrite
#pragma unroll
            for (int u = 0; u < 8; u++)
                Os[(cg * 8 + u) * 33 + px] = o[u];
        }
        __syncthreads();

        // --- coalesced NCHW store ---
#pragma unroll
        for (int u = 0; u < 8; u++) {
            int idx = u * 256 + tid;
            int co  = idx >> 5;
            int px  = idx & 31;
            out[((b * 64 + co) * 128 + i) * 128 + j0 + px] = Os[co * 33 + px];
        }
    }
}

// ---------------------------------------------------------------------------
extern "C" void kernel_launch(void* const* d_in, const int* in_sizes, int n_in,
                              void* d_out, int out_size) {
    const float* x    = (const float*)d_in[0];
    const float* Woff = (const float*)d_in[1];
    const float* boff = (const float*)d_in[2];
    const float* Wc   = (const float*)d_in[3];
    float* out = (float*)d_out;

    cudaFuncSetAttribute(k_offsets, cudaFuncAttributeMaxDynamicSharedMemorySize, K1_SMEM_BYTES);
    cudaFuncSetAttribute(k_main,    cudaFuncAttributeMaxDynamicSharedMemorySize, K2_SMEM_BYTES);

    dim3 tb0(32, 8);
    dim3 tg0(WW / 32, CIN / 32, BATCH * HH);
    k_transpose<<<tg0, tb0>>>(x);

    dim3 tg1(WW / 16, HH / 16, BATCH);
    k_offsets<<<tg1, 256, K1_SMEM_BYTES>>>(x, Woff, boff);

    k_main<<<148, 256, K2_SMEM_BYTES>>>(Wc, out);
}